// round 6
// baseline (speedup 1.0000x reference)
#include <cuda_runtime.h>

#define NPTS 8192
#define BATCH 2
#define KK 20
#define G 32
#define NCELL (G*G*G)
#define FULLMASK 0xffffffffu

// -------- device scratch (no allocations allowed) --------
__device__ float  g_bbox[BATCH * 8];        // minx,miny,minz,maxx,maxy,maxz per batch
__device__ int    g_cellcnt[BATCH * NCELL];
__device__ int    g_cellptr[BATCH * NCELL]; // exclusive start after scan -> end after scatter
__device__ float4 g_spts[BATCH * NPTS];     // grid-sorted (x,y,z, -0.5*||p||^2)
__device__ int    g_sidx[BATCH * NPTS];     // original index of sorted point
__device__ int    g_idx[BATCH * NPTS * KK];
__device__ float  g_pre[BATCH * NPTS * 64];
__device__ float  g_ctr[BATCH * NPTS * 64];
__device__ float  g_cat[BATCH * NPTS * 192];

__device__ __forceinline__ float leaky(float v) { return fmaxf(v, 0.2f * v); }

__device__ __forceinline__ unsigned f2s(float f) {
    unsigned u = __float_as_uint(f);
    return u ^ (unsigned)(((int)u >> 31) | 0x80000000);
}
__device__ __forceinline__ float s2f(unsigned u) {
    unsigned x = u ^ (unsigned)(((int)(~u) >> 31) | 0x80000000);
    return __uint_as_float(x);
}

__device__ __forceinline__ int cell1d(float v, float mn, float inv) {
    int c = (int)((v - mn) * inv);
    return min(max(c, 0), G - 1);
}

// -------- grid build --------
__global__ void zero_kernel() {
    int id = blockIdx.x * 256 + threadIdx.x;
    if (id < BATCH * NCELL) g_cellcnt[id] = 0;
}

__global__ __launch_bounds__(256) void bbox_kernel(const float* __restrict__ x) {
    int b = blockIdx.x, t = threadIdx.x;
    const float* xb = x + b * 6 * NPTS;
    float lmn[3] = {1e30f, 1e30f, 1e30f};
    float lmx[3] = {-1e30f, -1e30f, -1e30f};
    for (int j = t; j < NPTS; j += 256) {
#pragma unroll
        for (int a = 0; a < 3; ++a) {
            float v = xb[a * NPTS + j];
            lmn[a] = fminf(lmn[a], v);
            lmx[a] = fmaxf(lmx[a], v);
        }
    }
    __shared__ float sm[256];
#pragma unroll
    for (int i = 0; i < 6; ++i) {
        float val = (i < 3) ? lmn[i] : -lmx[i - 3];
        sm[t] = val;
        __syncthreads();
        for (int d = 128; d; d >>= 1) {
            if (t < d) sm[t] = fminf(sm[t], sm[t + d]);
            __syncthreads();
        }
        if (t == 0) g_bbox[b * 8 + i] = (i < 3) ? sm[0] : -sm[0];
        __syncthreads();
    }
}

__global__ void hist_kernel(const float* __restrict__ x) {
    int id = blockIdx.x * 256 + threadIdx.x;   // 0..16383
    int b = id >> 13, j = id & (NPTS - 1);
    const float* xb = x + b * 6 * NPTS;
    float px = xb[j], py = xb[NPTS + j], pz = xb[2 * NPTS + j];
    float mnx = g_bbox[b * 8], mny = g_bbox[b * 8 + 1], mnz = g_bbox[b * 8 + 2];
    float ivx = (float)G / (g_bbox[b * 8 + 3] - mnx + 1e-9f);
    float ivy = (float)G / (g_bbox[b * 8 + 4] - mny + 1e-9f);
    float ivz = (float)G / (g_bbox[b * 8 + 5] - mnz + 1e-9f);
    int cid = (cell1d(pz, mnz, ivz) * G + cell1d(py, mny, ivy)) * G + cell1d(px, mnx, ivx);
    atomicAdd(&g_cellcnt[b * NCELL + cid], 1);
}

__global__ __launch_bounds__(1024) void scan_kernel() {
    int b = blockIdx.x, t = threadIdx.x;
    int base = b * NCELL;
    int c0 = t * 32;
    int cnts[32];
    int local = 0;
#pragma unroll
    for (int k = 0; k < 32; ++k) { cnts[k] = g_cellcnt[base + c0 + k]; local += cnts[k]; }
    __shared__ int s[1024];
    s[t] = local;
    __syncthreads();
    for (int d = 1; d < 1024; d <<= 1) {
        int v = s[t];
        if (t >= d) v += s[t - d];
        __syncthreads();
        s[t] = v;
        __syncthreads();
    }
    int run = s[t] - local;   // exclusive prefix
#pragma unroll
    for (int k = 0; k < 32; ++k) { g_cellptr[base + c0 + k] = run; run += cnts[k]; }
}

__global__ void scatter_kernel(const float* __restrict__ x) {
    int id = blockIdx.x * 256 + threadIdx.x;
    int b = id >> 13, j = id & (NPTS - 1);
    const float* xb = x + b * 6 * NPTS;
    float px = xb[j], py = xb[NPTS + j], pz = xb[2 * NPTS + j];
    float mnx = g_bbox[b * 8], mny = g_bbox[b * 8 + 1], mnz = g_bbox[b * 8 + 2];
    float ivx = (float)G / (g_bbox[b * 8 + 3] - mnx + 1e-9f);
    float ivy = (float)G / (g_bbox[b * 8 + 4] - mny + 1e-9f);
    float ivz = (float)G / (g_bbox[b * 8 + 5] - mnz + 1e-9f);
    int cid = (cell1d(pz, mnz, ivz) * G + cell1d(py, mny, ivy)) * G + cell1d(px, mnx, ivx);
    int pos = atomicAdd(&g_cellptr[b * NCELL + cid], 1);
    float w = -0.5f * (px * px + py * py + pz * pz);
    g_spts[b * NPTS + pos] = make_float4(px, py, pz, w);
    g_sidx[b * NPTS + pos] = j;
}

// -------- KNN: warp per query, expanding-shell exact search --------
// Key e = dot(q,c) - 0.5*||c||^2 (maximize e <=> minimize dist). List: 20 lane slots,
// lanes>=KK hold +inf-coded sentinels never evicted. While nf<KK mnv=-inf (everything
// pushes, evicting the 0-coded empty slots first). Stop after shell s when the list is
// full and worst dist^2 <= (s*cellmin)^2 (any unscanned cell is at least s*cellmin away).
__global__ __launch_bounds__(256) void knn_grid_kernel(const float* __restrict__ x) {
    const int b = blockIdx.y;
    const int warp = threadIdx.x >> 5;
    const int lane = threadIdx.x & 31;
    const int n = blockIdx.x * 8 + warp;
    const float* xb = x + b * 6 * NPTS;

    float qx = xb[n], qy = xb[NPTS + n], qz = xb[2 * NPTS + n];
    float qxx = qx * qx + qy * qy + qz * qz;

    float mnx = g_bbox[b * 8], mny = g_bbox[b * 8 + 1], mnz = g_bbox[b * 8 + 2];
    float rx = g_bbox[b * 8 + 3] - mnx + 1e-9f;
    float ry = g_bbox[b * 8 + 4] - mny + 1e-9f;
    float rz = g_bbox[b * 8 + 5] - mnz + 1e-9f;
    float ivx = (float)G / rx, ivy = (float)G / ry, ivz = (float)G / rz;
    float smin = fminf(rx, fminf(ry, rz)) * (1.0f / (float)G);
    int qcx = cell1d(qx, mnx, ivx), qcy = cell1d(qy, mny, ivy), qcz = cell1d(qz, mnz, ivz);

    unsigned kuv = (lane < KK) ? 0u : 0xFFFFFFFFu;
    int kj = 0;
    int mnl = 0, nf = 0;
    float mnv = __int_as_float(0xff800000);   // -inf while list not full

    const float4* sp = g_spts + b * NPTS;
    const int*    si = g_sidx + b * NPTS;
    const int*    cend = g_cellptr + b * NCELL;
    const int*    ccnt = g_cellcnt + b * NCELL;

    for (int s = 0; s < G; ++s) {
        int x0 = max(qcx - s, 0), x1 = min(qcx + s, G - 1);
        int y0 = max(qcy - s, 0), y1 = min(qcy + s, G - 1);
        int z0 = max(qcz - s, 0), z1 = min(qcz + s, G - 1);
        int bx = x1 - x0 + 1, by = y1 - y0 + 1, bz = z1 - z0 + 1;
        int tot = bx * by * bz;
        for (int basec = 0; basec < tot; basec += 32) {
            int t = basec + lane;
            int cstart = 0, ccount = 0;
            if (t < tot) {
                int ix = x0 + t % bx;
                int t2 = t / bx;
                int iy = y0 + t2 % by;
                int iz = z0 + t2 / by;
                int ch = max(abs(ix - qcx), max(abs(iy - qcy), abs(iz - qcz)));
                if (ch == s) {
                    int cid = (iz * G + iy) * G + ix;
                    ccount = ccnt[cid];
                    cstart = cend[cid] - ccount;
                }
            }
            unsigned cm = __ballot_sync(FULLMASK, ccount > 0);
            while (cm) {
                int srcl = __ffs(cm) - 1; cm &= cm - 1;
                int s0 = __shfl_sync(FULLMASK, cstart, srcl);
                int c0 = __shfl_sync(FULLMASK, ccount, srcl);
                for (int p0 = 0; p0 < c0; p0 += 32) {
                    int pi = p0 + lane;
                    bool pv = pi < c0;
                    float e = __int_as_float(0xff800000);
                    int cj = 0;
                    if (pv) {
                        float4 pt = sp[s0 + pi];
                        cj = si[s0 + pi];
                        e = fmaf(qx, pt.x, fmaf(qy, pt.y, fmaf(qz, pt.z, pt.w)));
                    }
                    unsigned mask = __ballot_sync(FULLMASK, pv && (e > mnv));
                    while (mask) {
                        int src = __ffs(mask) - 1; mask &= mask - 1;
                        float ce = __shfl_sync(FULLMASK, e, src);
                        int  cjj = __shfl_sync(FULLMASK, cj, src);
                        if (ce > mnv) {
                            if (lane == mnl) { kuv = f2s(ce); kj = cjj; }
                            unsigned mn = __reduce_min_sync(FULLMASK, kuv);
                            unsigned bal = __ballot_sync(FULLMASK, kuv == mn);
                            mnl = __ffs(bal) - 1;
                            nf++;
                            mnv = (nf >= KK) ? s2f(mn) : __int_as_float(0xff800000);
                        }
                    }
                }
            }
        }
        // termination: worst kept dist^2 vs guaranteed min dist of unscanned cells
        float r = (float)s * smin;
        if (nf >= KK && (qxx - 2.0f * mnv) <= r * r) break;
    }

    if (lane < KK) g_idx[(b * NPTS + n) * KK + lane] = kj;
}

// -------- conv1 pre --------
__global__ __launch_bounds__(256) void pre1_kernel(const float* __restrict__ x,
                                                   const float* __restrict__ W1) {
    __shared__ float sW[384];
    for (int t = threadIdx.x; t < 384; t += 256)
        sW[t] = W1[t] * (((t % 6) < 3) ? 10.0f : 1.0f);
    __syncthreads();
    int o = threadIdx.x & 63;
    int pid = blockIdx.x * 4 + (threadIdx.x >> 6);
    int b = pid >> 13, j = pid & (NPTS - 1);
    const float* xb = x + b * 6 * NPTS;
    float acc = 0.f;
#pragma unroll
    for (int c = 0; c < 6; ++c) acc = fmaf(sW[o * 6 + c], xb[c * NPTS + j], acc);
    g_pre[pid * 64 + o] = acc;
}

// -------- conv1 gather-max (lane-held idx + shfl distribution) --------
__global__ __launch_bounds__(256) void conv1_kernel(const float* __restrict__ x,
                                                    const float* __restrict__ W1,
                                                    const float* __restrict__ b1) {
    int b = blockIdx.y;
    int lane = threadIdx.x & 31;
    int n = blockIdx.x * 8 + (threadIdx.x >> 5);
    int pid = b * NPTS + n;
    int jk = 0; float mx = 0.f, my = 0.f, mz = 0.f;
    if (lane < KK) {
        jk = g_idx[pid * KK + lane];
        const float* xb = x + b * 6 * NPTS;
        mx = xb[jk]; my = xb[NPTS + jk]; mz = xb[2 * NPTS + jk];
    }
#pragma unroll
    for (int off = 16; off; off >>= 1) {
        mx += __shfl_xor_sync(FULLMASK, mx, off);
        my += __shfl_xor_sync(FULLMASK, my, off);
        mz += __shfl_xor_sync(FULLMASK, mz, off);
    }
    float m0 = mx / (float)KK, m1 = my / (float)KK, m2 = mz / (float)KK;
    int o0 = lane, o1 = lane + 32;
    float c0 = b1[o0] - 10.0f * (W1[o0 * 6] * m0 + W1[o0 * 6 + 1] * m1 + W1[o0 * 6 + 2] * m2);
    float c1 = b1[o1] - 10.0f * (W1[o1 * 6] * m0 + W1[o1 * 6 + 1] * m1 + W1[o1 * 6 + 2] * m2);
    float v0 = -1e30f, v1 = -1e30f;
    const float* pb = g_pre + b * NPTS * 64;
#pragma unroll
    for (int k = 0; k < KK; ++k) {
        int j = __shfl_sync(FULLMASK, jk, k);
        const float* p = pb + j * 64 + lane;
        v0 = fmaxf(v0, p[0]);
        v1 = fmaxf(v1, p[32]);
    }
    float* cp = g_cat + pid * 192;
    cp[o0] = leaky(v0 + c0);
    cp[o1] = leaky(v1 + c1);
}

// -------- conv2/3 pre --------
__global__ __launch_bounds__(256) void preC_kernel(const float* __restrict__ W,
                                                   const float* __restrict__ bias,
                                                   int in_off) {
    __shared__ float sWa[64][65];
    __shared__ float sWd[64][65];
    __shared__ float sX[32][64];
    for (int t = threadIdx.x; t < 4096; t += 256) {
        int oo = t >> 6, cc = t & 63;
        float wa = W[oo * 128 + cc];
        sWa[oo][cc] = wa;
        sWd[oo][cc] = W[oo * 128 + 64 + cc] - wa;
    }
    int p0 = blockIdx.x * 32;
    for (int t = threadIdx.x; t < 2048; t += 256) {
        int pp = t >> 6, cc = t & 63;
        sX[pp][cc] = g_cat[(p0 + pp) * 192 + in_off + cc];
    }
    __syncthreads();
    int o = threadIdx.x & 63, pg = threadIdx.x >> 6;
    float aA[8], aD[8];
#pragma unroll
    for (int i = 0; i < 8; ++i) { aA[i] = 0.f; aD[i] = 0.f; }
    for (int c = 0; c < 64; ++c) {
        float wa = sWa[o][c], wd = sWd[o][c];
#pragma unroll
        for (int i = 0; i < 8; ++i) {
            float xv = sX[pg + 4 * i][c];
            aA[i] = fmaf(wa, xv, aA[i]);
            aD[i] = fmaf(wd, xv, aD[i]);
        }
    }
    float bo = bias[o];
#pragma unroll
    for (int i = 0; i < 8; ++i) {
        int pid = p0 + pg + 4 * i;
        g_pre[pid * 64 + o] = aA[i];
        g_ctr[pid * 64 + o] = aD[i] + bo;
    }
}

// -------- conv2/3 gather-max --------
__global__ __launch_bounds__(256) void convG_kernel(int out_off) {
    int b = blockIdx.y;
    int lane = threadIdx.x & 31;
    int n = blockIdx.x * 8 + (threadIdx.x >> 5);
    int pid = b * NPTS + n;
    int jk = (lane < KK) ? g_idx[pid * KK + lane] : 0;
    float z0 = g_ctr[pid * 64 + lane];
    float z1 = g_ctr[pid * 64 + 32 + lane];
    float v0 = -1e30f, v1 = -1e30f;
    const float* pb = g_pre + b * NPTS * 64;
#pragma unroll
    for (int k = 0; k < KK; ++k) {
        int j = __shfl_sync(FULLMASK, jk, k);
        const float* p = pb + j * 64 + lane;
        v0 = fmaxf(v0, p[0]);
        v1 = fmaxf(v1, p[32]);
    }
    float* cp = g_cat + pid * 192 + out_off;
    cp[lane] = leaky(v0 + z0);
    cp[32 + lane] = leaky(v1 + z1);
}

// -------- final GEMM (scalar FFMA) --------
__global__ __launch_bounds__(256) void final_kernel(const float* __restrict__ W4,
                                                    const float* __restrict__ b4,
                                                    float* __restrict__ out) {
    __shared__ float sA[16][64];
    __shared__ float sB[16][128];
    int b = blockIdx.z;
    int obase = blockIdx.y * 64;
    int nbase = blockIdx.x * 128;
    int t = threadIdx.x;
    float acc[8][4];
#pragma unroll
    for (int i = 0; i < 8; ++i)
#pragma unroll
        for (int jq = 0; jq < 4; ++jq) acc[i][jq] = 0.f;
    int lo = t >> 2, lc = (t & 3) * 4;
    int o8l = (t >> 5) * 8, n4l = (t & 31) * 4;
    for (int c0 = 0; c0 < 192; c0 += 16) {
        float4 av = *(const float4*)(W4 + (obase + lo) * 192 + c0 + lc);
        sA[lc + 0][lo] = av.x; sA[lc + 1][lo] = av.y; sA[lc + 2][lo] = av.z; sA[lc + 3][lo] = av.w;
#pragma unroll
        for (int r = 0; r < 2; ++r) {
            int l = t + r * 256;
            int nn = l >> 2, cc = (l & 3) * 4;
            const float* src = g_cat + (b * NPTS + nbase + nn) * 192 + c0 + cc;
            float4 bv = *(const float4*)src;
            sB[cc + 0][nn] = bv.x; sB[cc + 1][nn] = bv.y; sB[cc + 2][nn] = bv.z; sB[cc + 3][nn] = bv.w;
        }
        __syncthreads();
#pragma unroll
        for (int c = 0; c < 16; ++c) {
            float a[8], bb[4];
#pragma unroll
            for (int i = 0; i < 8; ++i) a[i] = sA[c][o8l + i];
#pragma unroll
            for (int jq = 0; jq < 4; ++jq) bb[jq] = sB[c][n4l + jq];
#pragma unroll
            for (int i = 0; i < 8; ++i)
#pragma unroll
                for (int jq = 0; jq < 4; ++jq)
                    acc[i][jq] = fmaf(a[i], bb[jq], acc[i][jq]);
        }
        __syncthreads();
    }
    int o8 = obase + o8l, n4 = nbase + n4l;
#pragma unroll
    for (int i = 0; i < 8; ++i) {
        float bo = b4[o8 + i];
        float4 v;
        v.x = leaky(acc[i][0] + bo);
        v.y = leaky(acc[i][1] + bo);
        v.z = leaky(acc[i][2] + bo);
        v.w = leaky(acc[i][3] + bo);
        *(float4*)(out + ((long)(b * 256 + o8 + i)) * NPTS + n4) = v;
    }
}

extern "C" void kernel_launch(void* const* d_in, const int* in_sizes, int n_in,
                              void* d_out, int out_size) {
    const float* x  = (const float*)d_in[0];
    const float* W1 = (const float*)d_in[1];
    const float* b1 = (const float*)d_in[2];
    const float* W2 = (const float*)d_in[3];
    const float* b2 = (const float*)d_in[4];
    const float* W3 = (const float*)d_in[5];
    const float* b3 = (const float*)d_in[6];
    const float* W4 = (const float*)d_in[7];
    const float* b4 = (const float*)d_in[8];
    float* out = (float*)d_out;

    zero_kernel<<<(BATCH * NCELL + 255) / 256, 256>>>();
    bbox_kernel<<<2, 256>>>(x);
    hist_kernel<<<64, 256>>>(x);
    scan_kernel<<<2, 1024>>>();
    scatter_kernel<<<64, 256>>>(x);
    knn_grid_kernel<<<dim3(1024, 2), 256>>>(x);
    pre1_kernel<<<4096, 256>>>(x, W1);
    conv1_kernel<<<dim3(1024, 2), 256>>>(x, W1, b1);
    preC_kernel<<<512, 256>>>(W2, b2, 0);
    convG_kernel<<<dim3(1024, 2), 256>>>(64);
    preC_kernel<<<512, 256>>>(W3, b3, 64);
    convG_kernel<<<dim3(1024, 2), 256>>>(128);
    final_kernel<<<dim3(64, 4, 2), 256>>>(W4, b4, out);
}

// round 7
// speedup vs baseline: 1.9210x; 1.9210x over previous
#include <cuda_runtime.h>

#define NPTS 8192
#define BATCH 2
#define KK 20
#define FULLMASK 0xffffffffu

// -------- device scratch (no allocations allowed) --------
__device__ float4 g_pts4[BATCH * NPTS];      // (x, y, z, -0.5*||p||^2)
__device__ int    g_idx[BATCH * NPTS * KK];
__device__ float  g_pre[BATCH * NPTS * 64];
__device__ float  g_ctr[BATCH * NPTS * 64];
__device__ float  g_cat[BATCH * NPTS * 192];

__device__ __forceinline__ float leaky(float v) { return fmaxf(v, 0.2f * v); }

// packed f32x2 fused multiply-add (PTX-only on Blackwell)
__device__ __forceinline__ void fma2(unsigned long long& d, unsigned long long a,
                                     unsigned long long b) {
    asm("fma.rn.f32x2 %0, %1, %2, %0;" : "+l"(d) : "l"(a), "l"(b));
}
__device__ __forceinline__ float2 unpack2(unsigned long long v) {
    float lo, hi;
    asm("mov.b64 {%0, %1}, %2;" : "=f"(lo), "=f"(hi) : "l"(v));
    return make_float2(lo, hi);
}

__device__ __forceinline__ unsigned f2s(float f) {
    unsigned u = __float_as_uint(f);
    return u ^ (unsigned)(((int)u >> 31) | 0x80000000);
}
__device__ __forceinline__ float s2f(unsigned u) {
    unsigned x = u ^ (unsigned)(((int)(~u) >> 31) | 0x80000000);
    return __uint_as_float(x);
}

// -------- pack points: (x,y,z,-0.5*xx) --------
__global__ void pts4_kernel(const float* __restrict__ x) {
    int id = blockIdx.x * 256 + threadIdx.x;  // 0..16383
    int b = id >> 13, j = id & (NPTS - 1);
    const float* xb = x + b * 6 * NPTS;
    float a = xb[j], c = xb[NPTS + j], e = xb[2 * NPTS + j];
    g_pts4[id] = make_float4(a, c, e, -0.5f * (a * a + c * c + e * e));
}

// -------- KNN: 8 queries per warp, streaming replace-min top-20 (REDUX push) --------
// Key e = dot(q,c) - 0.5*||c||^2; maximize e == minimize dist. Same candidate order
// as brute-force reference scan (j ascending), so tie-breaking matches prior rounds.
__global__ __launch_bounds__(256) void knn_kernel() {
    __shared__ float4 tile[2048];
    const int b = blockIdx.y;
    const int warp = threadIdx.x >> 5;
    const int lane = threadIdx.x & 31;
    const int qbase = blockIdx.x * 64 + warp * 8;   // 8 queries per warp
    const float4* pts = g_pts4 + b * NPTS;

    float qx[8], qy[8], qz[8];
#pragma unroll
    for (int q = 0; q < 8; ++q) {
        float4 p = pts[qbase + q];
        qx[q] = p.x; qy[q] = p.y; qz[q] = p.z;
    }

    unsigned kuv[8];
    int kj[8];
    float mnv[8];
    int mnl[8];

    // ---- prefill with candidates j = 0..19 (lane slots), then push j = 20..31 ----
    {
        float4 c = pts[lane];
#pragma unroll
        for (int q = 0; q < 8; ++q) {
            float e = fmaf(qx[q], c.x, fmaf(qy[q], c.y, fmaf(qz[q], c.z, c.w)));
            kuv[q] = (lane < KK) ? f2s(e) : 0xFFFFFFFFu;
            kj[q] = lane;
            unsigned mn = __reduce_min_sync(FULLMASK, kuv[q]);
            unsigned bal = __ballot_sync(FULLMASK, kuv[q] == mn);
            mnl[q] = __ffs(bal) - 1;
            mnv[q] = s2f(mn);
            // push candidates carried by lanes 20..31
            unsigned mask = __ballot_sync(FULLMASK, (lane >= KK) && (e > mnv[q]));
            while (mask) {
                int src = __ffs(mask) - 1; mask &= mask - 1;
                float ce = __shfl_sync(FULLMASK, e, src);
                if (ce > mnv[q]) {
                    if (lane == mnl[q]) { kuv[q] = f2s(ce); kj[q] = src; }
                    unsigned mn2 = __reduce_min_sync(FULLMASK, kuv[q]);
                    unsigned bal2 = __ballot_sync(FULLMASK, kuv[q] == mn2);
                    mnl[q] = __ffs(bal2) - 1;
                    mnv[q] = s2f(mn2);
                }
            }
        }
    }

    // ---- main streaming loop over smem tiles ----
    for (int t = 0; t < NPTS; t += 2048) {
        __syncthreads();
        for (int i = threadIdx.x; i < 2048; i += 256)
            tile[i] = pts[t + i];
        __syncthreads();
        int istart = (t == 0) ? (32 + lane) : lane;
        for (int i = istart; i < 2048; i += 32) {
            float4 c = tile[i];
            int j = t + i;
            float ed[8];
            unsigned pb = 0;
#pragma unroll
            for (int q = 0; q < 8; ++q) {
                ed[q] = fmaf(qx[q], c.x, fmaf(qy[q], c.y, fmaf(qz[q], c.z, c.w)));
                pb |= (ed[q] > mnv[q]) ? (1u << q) : 0u;
            }
            if (__any_sync(FULLMASK, pb)) {
#pragma unroll
                for (int q = 0; q < 8; ++q) {
                    unsigned mask = __ballot_sync(FULLMASK, (pb >> q) & 1u);
                    while (mask) {
                        int src = __ffs(mask) - 1; mask &= mask - 1;
                        float ce = __shfl_sync(FULLMASK, ed[q], src);
                        int   cj = __shfl_sync(FULLMASK, j, src);
                        if (ce > mnv[q]) {
                            if (lane == mnl[q]) { kuv[q] = f2s(ce); kj[q] = cj; }
                            unsigned mn = __reduce_min_sync(FULLMASK, kuv[q]);
                            unsigned bal = __ballot_sync(FULLMASK, kuv[q] == mn);
                            mnl[q] = __ffs(bal) - 1;
                            mnv[q] = s2f(mn);
                        }
                    }
                }
            }
        }
    }

#pragma unroll
    for (int q = 0; q < 8; ++q)
        if (lane < KK) g_idx[(b * NPTS + qbase + q) * KK + lane] = kj[q];
}

// -------- conv1 pre --------
__global__ __launch_bounds__(256) void pre1_kernel(const float* __restrict__ x,
                                                   const float* __restrict__ W1) {
    __shared__ float sW[384];
    for (int t = threadIdx.x; t < 384; t += 256)
        sW[t] = W1[t] * (((t % 6) < 3) ? 10.0f : 1.0f);
    __syncthreads();
    int o = threadIdx.x & 63;
    int pid = blockIdx.x * 4 + (threadIdx.x >> 6);
    int b = pid >> 13, j = pid & (NPTS - 1);
    const float* xb = x + b * 6 * NPTS;
    float acc = 0.f;
#pragma unroll
    for (int c = 0; c < 6; ++c) acc = fmaf(sW[o * 6 + c], xb[c * NPTS + j], acc);
    g_pre[pid * 64 + o] = acc;
}

// -------- conv1 gather-max (lane-held idx + shfl distribution) --------
__global__ __launch_bounds__(256) void conv1_kernel(const float* __restrict__ x,
                                                    const float* __restrict__ W1,
                                                    const float* __restrict__ b1) {
    int b = blockIdx.y;
    int lane = threadIdx.x & 31;
    int n = blockIdx.x * 8 + (threadIdx.x >> 5);
    int pid = b * NPTS + n;
    int jk = 0; float mx = 0.f, my = 0.f, mz = 0.f;
    if (lane < KK) {
        jk = g_idx[pid * KK + lane];
        const float* xb = x + b * 6 * NPTS;
        mx = xb[jk]; my = xb[NPTS + jk]; mz = xb[2 * NPTS + jk];
    }
#pragma unroll
    for (int off = 16; off; off >>= 1) {
        mx += __shfl_xor_sync(FULLMASK, mx, off);
        my += __shfl_xor_sync(FULLMASK, my, off);
        mz += __shfl_xor_sync(FULLMASK, mz, off);
    }
    float m0 = mx / (float)KK, m1 = my / (float)KK, m2 = mz / (float)KK;
    int o0 = lane, o1 = lane + 32;
    float c0 = b1[o0] - 10.0f * (W1[o0 * 6] * m0 + W1[o0 * 6 + 1] * m1 + W1[o0 * 6 + 2] * m2);
    float c1 = b1[o1] - 10.0f * (W1[o1 * 6] * m0 + W1[o1 * 6 + 1] * m1 + W1[o1 * 6 + 2] * m2);
    float v0 = -1e30f, v1 = -1e30f;
    const float* pb = g_pre + b * NPTS * 64;
#pragma unroll
    for (int k = 0; k < KK; ++k) {
        int j = __shfl_sync(FULLMASK, jk, k);
        const float* p = pb + j * 64 + lane;
        v0 = fmaxf(v0, p[0]);
        v1 = fmaxf(v1, p[32]);
    }
    float* cp = g_cat + pid * 192;
    cp[o0] = leaky(v0 + c0);
    cp[o1] = leaky(v1 + c1);
}

// -------- conv2/3 pre (scalar, proven) --------
__global__ __launch_bounds__(256) void preC_kernel(const float* __restrict__ W,
                                                   const float* __restrict__ bias,
                                                   int in_off) {
    __shared__ float sWa[64][65];
    __shared__ float sWd[64][65];
    __shared__ float sX[32][64];
    for (int t = threadIdx.x; t < 4096; t += 256) {
        int oo = t >> 6, cc = t & 63;
        float wa = W[oo * 128 + cc];
        sWa[oo][cc] = wa;
        sWd[oo][cc] = W[oo * 128 + 64 + cc] - wa;
    }
    int p0 = blockIdx.x * 32;
    for (int t = threadIdx.x; t < 2048; t += 256) {
        int pp = t >> 6, cc = t & 63;
        sX[pp][cc] = g_cat[(p0 + pp) * 192 + in_off + cc];
    }
    __syncthreads();
    int o = threadIdx.x & 63, pg = threadIdx.x >> 6;
    float aA[8], aD[8];
#pragma unroll
    for (int i = 0; i < 8; ++i) { aA[i] = 0.f; aD[i] = 0.f; }
    for (int c = 0; c < 64; ++c) {
        float wa = sWa[o][c], wd = sWd[o][c];
#pragma unroll
        for (int i = 0; i < 8; ++i) {
            float xv = sX[pg + 4 * i][c];
            aA[i] = fmaf(wa, xv, aA[i]);
            aD[i] = fmaf(wd, xv, aD[i]);
        }
    }
    float bo = bias[o];
#pragma unroll
    for (int i = 0; i < 8; ++i) {
        int pid = p0 + pg + 4 * i;
        g_pre[pid * 64 + o] = aA[i];
        g_ctr[pid * 64 + o] = aD[i] + bo;
    }
}

// -------- conv2/3 gather-max --------
__global__ __launch_bounds__(256) void convG_kernel(int out_off) {
    int b = blockIdx.y;
    int lane = threadIdx.x & 31;
    int n = blockIdx.x * 8 + (threadIdx.x >> 5);
    int pid = b * NPTS + n;
    int jk = (lane < KK) ? g_idx[pid * KK + lane] : 0;
    float z0 = g_ctr[pid * 64 + lane];
    float z1 = g_ctr[pid * 64 + 32 + lane];
    float v0 = -1e30f, v1 = -1e30f;
    const float* pb = g_pre + b * NPTS * 64;
#pragma unroll
    for (int k = 0; k < KK; ++k) {
        int j = __shfl_sync(FULLMASK, jk, k);
        const float* p = pb + j * 64 + lane;
        v0 = fmaxf(v0, p[0]);
        v1 = fmaxf(v1, p[32]);
    }
    float* cp = g_cat + pid * 192 + out_off;
    cp[lane] = leaky(v0 + z0);
    cp[32 + lane] = leaky(v1 + z1);
}

// -------- final GEMM with FFMA2 (isolated retest) --------
__global__ __launch_bounds__(256) void final_kernel(const float* __restrict__ W4,
                                                    const float* __restrict__ b4,
                                                    float* __restrict__ out) {
    __shared__ float2 sA2[16][64];   // duplicated (a,a) pairs, [c][o]
    __shared__ float  sB[16][128];
    int b = blockIdx.z;
    int obase = blockIdx.y * 64;
    int nbase = blockIdx.x * 128;
    int t = threadIdx.x;
    unsigned long long acc2[8][2];
#pragma unroll
    for (int i = 0; i < 8; ++i) { acc2[i][0] = 0ull; acc2[i][1] = 0ull; }
    int lo = t >> 2, lc = (t & 3) * 4;
    int o8l = (t >> 5) * 8, n4l = (t & 31) * 4;
    for (int c0 = 0; c0 < 192; c0 += 16) {
        float4 av = *(const float4*)(W4 + (obase + lo) * 192 + c0 + lc);
        sA2[lc + 0][lo] = make_float2(av.x, av.x);
        sA2[lc + 1][lo] = make_float2(av.y, av.y);
        sA2[lc + 2][lo] = make_float2(av.z, av.z);
        sA2[lc + 3][lo] = make_float2(av.w, av.w);
#pragma unroll
        for (int r = 0; r < 2; ++r) {
            int l = t + r * 256;
            int nn = l >> 2, cc = (l & 3) * 4;
            const float* src = g_cat + (b * NPTS + nbase + nn) * 192 + c0 + cc;
            float4 bv = *(const float4*)src;
            sB[cc + 0][nn] = bv.x; sB[cc + 1][nn] = bv.y; sB[cc + 2][nn] = bv.z; sB[cc + 3][nn] = bv.w;
        }
        __syncthreads();
#pragma unroll
        for (int c = 0; c < 16; ++c) {
            unsigned long long a2[8], b2[2];
#pragma unroll
            for (int i = 0; i < 8; ++i)
                a2[i] = *(const unsigned long long*)&sA2[c][o8l + i];
            b2[0] = *(const unsigned long long*)&sB[c][n4l];
            b2[1] = *(const unsigned long long*)&sB[c][n4l + 2];
#pragma unroll
            for (int i = 0; i < 8; ++i) {
                fma2(acc2[i][0], a2[i], b2[0]);
                fma2(acc2[i][1], a2[i], b2[1]);
            }
        }
        __syncthreads();
    }
    int o8 = obase + o8l, n4 = nbase + n4l;
#pragma unroll
    for (int i = 0; i < 8; ++i) {
        float bo = b4[o8 + i];
        float2 p0 = unpack2(acc2[i][0]);
        float2 p1 = unpack2(acc2[i][1]);
        float4 v;
        v.x = leaky(p0.x + bo);
        v.y = leaky(p0.y + bo);
        v.z = leaky(p1.x + bo);
        v.w = leaky(p1.y + bo);
        *(float4*)(out + ((long)(b * 256 + o8 + i)) * NPTS + n4) = v;
    }
}

extern "C" void kernel_launch(void* const* d_in, const int* in_sizes, int n_in,
                              void* d_out, int out_size) {
    const float* x  = (const float*)d_in[0];
    const float* W1 = (const float*)d_in[1];
    const float* b1 = (const float*)d_in[2];
    const float* W2 = (const float*)d_in[3];
    const float* b2 = (const float*)d_in[4];
    const float* W3 = (const float*)d_in[5];
    const float* b3 = (const float*)d_in[6];
    const float* W4 = (const float*)d_in[7];
    const float* b4 = (const float*)d_in[8];
    float* out = (float*)d_out;

    pts4_kernel<<<64, 256>>>(x);
    knn_kernel<<<dim3(128, 2), 256>>>();
    pre1_kernel<<<4096, 256>>>(x, W1);
    conv1_kernel<<<dim3(1024, 2), 256>>>(x, W1, b1);
    preC_kernel<<<512, 256>>>(W2, b2, 0);
    convG_kernel<<<dim3(1024, 2), 256>>>(64);
    preC_kernel<<<512, 256>>>(W3, b3, 64);
    convG_kernel<<<dim3(1024, 2), 256>>>(128);
    final_kernel<<<dim3(64, 4, 2), 256>>>(W4, b4, out);
}

// round 8
// speedup vs baseline: 2.4590x; 1.2801x over previous
#include <cuda_runtime.h>

#define NPTS 8192
#define BATCH 2
#define KK 20
#define FULLMASK 0xffffffffu

// -------- device scratch (no allocations allowed) --------
__device__ float4 g_pts4[BATCH * NPTS];      // (x, y, z, ||p||^2)
__device__ int    g_idx[BATCH * NPTS * KK];
__device__ float  g_pre[BATCH * NPTS * 64];
__device__ float  g_ctr[BATCH * NPTS * 64];
__device__ float  g_cat[BATCH * NPTS * 192];

__device__ __forceinline__ float leaky(float v) { return fmaxf(v, 0.2f * v); }

__device__ __forceinline__ unsigned f2s(float f) {
    unsigned u = __float_as_uint(f);
    return u ^ (unsigned)(((int)u >> 31) | 0x80000000);
}
__device__ __forceinline__ float s2f(unsigned u) {
    unsigned x = u ^ (unsigned)(((int)(~u) >> 31) | 0x80000000);
    return __uint_as_float(x);
}

// -------- pack points: (x,y,z,xx) --------
__global__ void pts4_kernel(const float* __restrict__ x) {
    int id = blockIdx.x * 256 + threadIdx.x;  // 0..16383
    int b = id >> 13, j = id & (NPTS - 1);
    const float* xb = x + b * 6 * NPTS;
    float a = xb[j], c = xb[NPTS + j], e = xb[2 * NPTS + j];
    g_pts4[id] = make_float4(a, c, e, a * a + c * c + e * e);
}

// -------- KNN: 4 queries per warp, streaming replace-min top-20 (REDUX push) --------
// Key arithmetic IDENTICAL to the proven R5 kernel:
//   dot = fmaf(qx,cx, fmaf(qy,cy, qz*cz));  e = dot + (-0.5f * xx)
// (-0.5*xx is exact scaling, so prefill's fmaf(-0.5,xx,dot) == dot + hw bitwise).
__global__ __launch_bounds__(256) void knn_kernel() {
    __shared__ float4 tile[2048];
    const int b = blockIdx.y;
    const int warp = threadIdx.x >> 5;
    const int lane = threadIdx.x & 31;
    const int qbase = blockIdx.x * 32 + warp * 4;   // 4 queries per warp
    const float4* pts = g_pts4 + b * NPTS;

    float qx[4], qy[4], qz[4];
#pragma unroll
    for (int q = 0; q < 4; ++q) {
        float4 p = pts[qbase + q];
        qx[q] = p.x; qy[q] = p.y; qz[q] = p.z;
    }

    unsigned kuv[4];
    int kj[4];
    float mnv[4];
    int mnl[4];

    // ---- prefill slots with candidates j = 0..19; then push j = 20..31 ----
    {
        float4 c = pts[lane];
        float cx = c.x, cy = c.y, cz = c.z, cw = c.w;
#pragma unroll
        for (int q = 0; q < 4; ++q) {
            float dot = fmaf(qx[q], cx, fmaf(qy[q], cy, qz[q] * cz));
            float e = fmaf(-0.5f, cw, dot);
            kuv[q] = (lane < KK) ? f2s(e) : 0xFFFFFFFFu;
            kj[q] = lane;
            unsigned mn = __reduce_min_sync(FULLMASK, kuv[q]);
            unsigned bal = __ballot_sync(FULLMASK, kuv[q] == mn);
            mnl[q] = __ffs(bal) - 1;
            mnv[q] = s2f(mn);
            unsigned mask = __ballot_sync(FULLMASK, (lane >= KK) && (e > mnv[q]));
            while (mask) {
                int src = __ffs(mask) - 1; mask &= mask - 1;
                float ce = __shfl_sync(FULLMASK, e, src);
                if (ce > mnv[q]) {
                    if (lane == mnl[q]) { kuv[q] = f2s(ce); kj[q] = src; }
                    unsigned mn2 = __reduce_min_sync(FULLMASK, kuv[q]);
                    unsigned bal2 = __ballot_sync(FULLMASK, kuv[q] == mn2);
                    mnl[q] = __ffs(bal2) - 1;
                    mnv[q] = s2f(mn2);
                }
            }
        }
    }

    // ---- main streaming loop over smem tiles ----
    for (int t = 0; t < NPTS; t += 2048) {
        __syncthreads();
        for (int i = threadIdx.x; i < 2048; i += 256)
            tile[i] = pts[t + i];
        __syncthreads();
        int istart = (t == 0) ? (32 + lane) : lane;
        for (int i = istart; i < 2048; i += 32) {
            float4 c = tile[i];
            int j = t + i;
            float ed[4];
            float hw = -0.5f * c.w;
#pragma unroll
            for (int q = 0; q < 4; ++q) {
                float dot = fmaf(qx[q], c.x, fmaf(qy[q], c.y, qz[q] * c.z));
                ed[q] = dot + hw;
            }
            bool pr0 = ed[0] > mnv[0], pr1 = ed[1] > mnv[1];
            bool pr2 = ed[2] > mnv[2], pr3 = ed[3] > mnv[3];
            if (__any_sync(FULLMASK, pr0 | pr1 | pr2 | pr3)) {
                bool prq[4] = {pr0, pr1, pr2, pr3};
#pragma unroll
                for (int q = 0; q < 4; ++q) {
                    unsigned mask = __ballot_sync(FULLMASK, prq[q]);
                    while (mask) {
                        int src = __ffs(mask) - 1; mask &= mask - 1;
                        float ce = __shfl_sync(FULLMASK, ed[q], src);
                        int   cj = __shfl_sync(FULLMASK, j, src);
                        if (ce > mnv[q]) {
                            if (lane == mnl[q]) { kuv[q] = f2s(ce); kj[q] = cj; }
                            unsigned mn = __reduce_min_sync(FULLMASK, kuv[q]);
                            unsigned bal = __ballot_sync(FULLMASK, kuv[q] == mn);
                            mnl[q] = __ffs(bal) - 1;
                            mnv[q] = s2f(mn);
                        }
                    }
                }
            }
        }
    }

#pragma unroll
    for (int q = 0; q < 4; ++q)
        if (lane < KK) g_idx[(b * NPTS + qbase + q) * KK + lane] = kj[q];
}

// -------- conv1 pre --------
__global__ __launch_bounds__(256) void pre1_kernel(const float* __restrict__ x,
                                                   const float* __restrict__ W1) {
    __shared__ float sW[384];
    for (int t = threadIdx.x; t < 384; t += 256)
        sW[t] = W1[t] * (((t % 6) < 3) ? 10.0f : 1.0f);
    __syncthreads();
    int o = threadIdx.x & 63;
    int pid = blockIdx.x * 4 + (threadIdx.x >> 6);
    int b = pid >> 13, j = pid & (NPTS - 1);
    const float* xb = x + b * 6 * NPTS;
    float acc = 0.f;
#pragma unroll
    for (int c = 0; c < 6; ++c) acc = fmaf(sW[o * 6 + c], xb[c * NPTS + j], acc);
    g_pre[pid * 64 + o] = acc;
}

// -------- conv1 gather-max (lane-held idx + shfl distribution) --------
__global__ __launch_bounds__(256) void conv1_kernel(const float* __restrict__ x,
                                                    const float* __restrict__ W1,
                                                    const float* __restrict__ b1) {
    int b = blockIdx.y;
    int lane = threadIdx.x & 31;
    int n = blockIdx.x * 8 + (threadIdx.x >> 5);
    int pid = b * NPTS + n;
    int jk = 0; float mx = 0.f, my = 0.f, mz = 0.f;
    if (lane < KK) {
        jk = g_idx[pid * KK + lane];
        const float* xb = x + b * 6 * NPTS;
        mx = xb[jk]; my = xb[NPTS + jk]; mz = xb[2 * NPTS + jk];
    }
#pragma unroll
    for (int off = 16; off; off >>= 1) {
        mx += __shfl_xor_sync(FULLMASK, mx, off);
        my += __shfl_xor_sync(FULLMASK, my, off);
        mz += __shfl_xor_sync(FULLMASK, mz, off);
    }
    float m0 = mx / (float)KK, m1 = my / (float)KK, m2 = mz / (float)KK;
    int o0 = lane, o1 = lane + 32;
    float c0 = b1[o0] - 10.0f * (W1[o0 * 6] * m0 + W1[o0 * 6 + 1] * m1 + W1[o0 * 6 + 2] * m2);
    float c1 = b1[o1] - 10.0f * (W1[o1 * 6] * m0 + W1[o1 * 6 + 1] * m1 + W1[o1 * 6 + 2] * m2);
    float v0 = -1e30f, v1 = -1e30f;
    const float* pb = g_pre + b * NPTS * 64;
#pragma unroll
    for (int k = 0; k < KK; ++k) {
        int j = __shfl_sync(FULLMASK, jk, k);
        const float* p = pb + j * 64 + lane;
        v0 = fmaxf(v0, p[0]);
        v1 = fmaxf(v1, p[32]);
    }
    float* cp = g_cat + pid * 192;
    cp[o0] = leaky(v0 + c0);
    cp[o1] = leaky(v1 + c1);
}

// -------- conv2/3 pre (scalar, proven) --------
__global__ __launch_bounds__(256) void preC_kernel(const float* __restrict__ W,
                                                   const float* __restrict__ bias,
                                                   int in_off) {
    __shared__ float sWa[64][65];
    __shared__ float sWd[64][65];
    __shared__ float sX[32][64];
    for (int t = threadIdx.x; t < 4096; t += 256) {
        int oo = t >> 6, cc = t & 63;
        float wa = W[oo * 128 + cc];
        sWa[oo][cc] = wa;
        sWd[oo][cc] = W[oo * 128 + 64 + cc] - wa;
    }
    int p0 = blockIdx.x * 32;
    for (int t = threadIdx.x; t < 2048; t += 256) {
        int pp = t >> 6, cc = t & 63;
        sX[pp][cc] = g_cat[(p0 + pp) * 192 + in_off + cc];
    }
    __syncthreads();
    int o = threadIdx.x & 63, pg = threadIdx.x >> 6;
    float aA[8], aD[8];
#pragma unroll
    for (int i = 0; i < 8; ++i) { aA[i] = 0.f; aD[i] = 0.f; }
    for (int c = 0; c < 64; ++c) {
        float wa = sWa[o][c], wd = sWd[o][c];
#pragma unroll
        for (int i = 0; i < 8; ++i) {
            float xv = sX[pg + 4 * i][c];
            aA[i] = fmaf(wa, xv, aA[i]);
            aD[i] = fmaf(wd, xv, aD[i]);
        }
    }
    float bo = bias[o];
#pragma unroll
    for (int i = 0; i < 8; ++i) {
        int pid = p0 + pg + 4 * i;
        g_pre[pid * 64 + o] = aA[i];
        g_ctr[pid * 64 + o] = aD[i] + bo;
    }
}

// -------- conv2/3 gather-max --------
__global__ __launch_bounds__(256) void convG_kernel(int out_off) {
    int b = blockIdx.y;
    int lane = threadIdx.x & 31;
    int n = blockIdx.x * 8 + (threadIdx.x >> 5);
    int pid = b * NPTS + n;
    int jk = (lane < KK) ? g_idx[pid * KK + lane] : 0;
    float z0 = g_ctr[pid * 64 + lane];
    float z1 = g_ctr[pid * 64 + 32 + lane];
    float v0 = -1e30f, v1 = -1e30f;
    const float* pb = g_pre + b * NPTS * 64;
#pragma unroll
    for (int k = 0; k < KK; ++k) {
        int j = __shfl_sync(FULLMASK, jk, k);
        const float* p = pb + j * 64 + lane;
        v0 = fmaxf(v0, p[0]);
        v1 = fmaxf(v1, p[32]);
    }
    float* cp = g_cat + pid * 192 + out_off;
    cp[lane] = leaky(v0 + z0);
    cp[32 + lane] = leaky(v1 + z1);
}

// -------- final GEMM (scalar FFMA, proven) --------
__global__ __launch_bounds__(256) void final_kernel(const float* __restrict__ W4,
                                                    const float* __restrict__ b4,
                                                    float* __restrict__ out) {
    __shared__ float sA[16][64];
    __shared__ float sB[16][128];
    int b = blockIdx.z;
    int obase = blockIdx.y * 64;
    int nbase = blockIdx.x * 128;
    int t = threadIdx.x;
    float acc[8][4];
#pragma unroll
    for (int i = 0; i < 8; ++i)
#pragma unroll
        for (int jq = 0; jq < 4; ++jq) acc[i][jq] = 0.f;
    int lo = t >> 2, lc = (t & 3) * 4;
    int o8l = (t >> 5) * 8, n4l = (t & 31) * 4;
    for (int c0 = 0; c0 < 192; c0 += 16) {
        float4 av = *(const float4*)(W4 + (obase + lo) * 192 + c0 + lc);
        sA[lc + 0][lo] = av.x; sA[lc + 1][lo] = av.y; sA[lc + 2][lo] = av.z; sA[lc + 3][lo] = av.w;
#pragma unroll
        for (int r = 0; r < 2; ++r) {
            int l = t + r * 256;
            int nn = l >> 2, cc = (l & 3) * 4;
            const float* src = g_cat + (b * NPTS + nbase + nn) * 192 + c0 + cc;
            float4 bv = *(const float4*)src;
            sB[cc + 0][nn] = bv.x; sB[cc + 1][nn] = bv.y; sB[cc + 2][nn] = bv.z; sB[cc + 3][nn] = bv.w;
        }
        __syncthreads();
#pragma unroll
        for (int c = 0; c < 16; ++c) {
            float a[8], bb[4];
#pragma unroll
            for (int i = 0; i < 8; ++i) a[i] = sA[c][o8l + i];
#pragma unroll
            for (int jq = 0; jq < 4; ++jq) bb[jq] = sB[c][n4l + jq];
#pragma unroll
            for (int i = 0; i < 8; ++i)
#pragma unroll
                for (int jq = 0; jq < 4; ++jq)
                    acc[i][jq] = fmaf(a[i], bb[jq], acc[i][jq]);
        }
        __syncthreads();
    }
    int o8 = obase + o8l, n4 = nbase + n4l;
#pragma unroll
    for (int i = 0; i < 8; ++i) {
        float bo = b4[o8 + i];
        float4 v;
        v.x = leaky(acc[i][0] + bo);
        v.y = leaky(acc[i][1] + bo);
        v.z = leaky(acc[i][2] + bo);
        v.w = leaky(acc[i][3] + bo);
        *(float4*)(out + ((long)(b * 256 + o8 + i)) * NPTS + n4) = v;
    }
}

extern "C" void kernel_launch(void* const* d_in, const int* in_sizes, int n_in,
                              void* d_out, int out_size) {
    const float* x  = (const float*)d_in[0];
    const float* W1 = (const float*)d_in[1];
    const float* b1 = (const float*)d_in[2];
    const float* W2 = (const float*)d_in[3];
    const float* b2 = (const float*)d_in[4];
    const float* W3 = (const float*)d_in[5];
    const float* b3 = (const float*)d_in[6];
    const float* W4 = (const float*)d_in[7];
    const float* b4 = (const float*)d_in[8];
    float* out = (float*)d_out;

    pts4_kernel<<<64, 256>>>(x);
    knn_kernel<<<dim3(256, 2), 256>>>();
    pre1_kernel<<<4096, 256>>>(x, W1);
    conv1_kernel<<<dim3(1024, 2), 256>>>(x, W1, b1);
    preC_kernel<<<512, 256>>>(W2, b2, 0);
    convG_kernel<<<dim3(1024, 2), 256>>>(64);
    preC_kernel<<<512, 256>>>(W3, b3, 64);
    convG_kernel<<<dim3(1024, 2), 256>>>(128);
    final_kernel<<<dim3(64, 4, 2), 256>>>(W4, b4, out);
}